// round 1
// baseline (speedup 1.0000x reference)
#include <cuda_runtime.h>
#include <cuda_bf16.h>
#include <math.h>

// Problem constants
#define BB 8
#define LL 512
#define DD 768
#define HH 12
#define DH 64
#define FF 3072
#define NL 6
#define NC 1
#define MM (BB*LL)   // 4096 rows

// ---------------- scratch (static device globals; no allocation) ----------------
__device__ float g_h [MM*DD];
__device__ float g_xn[MM*DD];
__device__ float g_q [MM*DD];
__device__ float g_k [MM*DD];
__device__ float g_v [MM*DD];
__device__ float g_ao[MM*DD];
__device__ float g_ff[MM*FF];

// ---------------- embedding + positional encoding ----------------
__global__ void embed_kernel(const int* __restrict__ x, const float* __restrict__ emb,
                             float* __restrict__ out) {
    int r = blockIdx.x;            // 0..4095  (b*L + l)
    int b = r / LL;
    int tok = x[r];
    const float* erow = emb + (size_t)tok * DD;
    float* orow = out + (size_t)r * DD;
    const float neg_log = -logf(10000.0f) / (float)DD;
    for (int j = 0; j < 3; j++) {
        int d = threadIdx.x + j * 256;
        int i2 = (d >> 1) << 1;                    // 2*i
        float div = expf((float)i2 * neg_log);
        float ang = (float)b * div;
        float pe = (d & 1) ? cosf(ang) : sinf(ang);
        orow[d] = erow[d] + pe;
    }
}

// ---------------- layernorm (one block per row) ----------------
__global__ void ln_kernel(const float* __restrict__ in, const float* __restrict__ g,
                          const float* __restrict__ be, float* __restrict__ out) {
    __shared__ float red[256];
    int r = blockIdx.x;
    int t = threadIdx.x;
    const float* xr = in + (size_t)r * DD;
    float v0 = xr[t], v1 = xr[t + 256], v2 = xr[t + 512];
    red[t] = v0 + v1 + v2;
    __syncthreads();
    for (int o = 128; o > 0; o >>= 1) { if (t < o) red[t] += red[t + o]; __syncthreads(); }
    float mean = red[0] * (1.0f / (float)DD);
    __syncthreads();
    float d0 = v0 - mean, d1 = v1 - mean, d2 = v2 - mean;
    red[t] = d0 * d0 + d1 * d1 + d2 * d2;
    __syncthreads();
    for (int o = 128; o > 0; o >>= 1) { if (t < o) red[t] += red[t + o]; __syncthreads(); }
    float var = red[0] * (1.0f / (float)DD);
    float rs = rsqrtf(var + 1e-5f);
    float* orow = out + (size_t)r * DD;
    orow[t]       = d0 * rs * g[t]       + be[t];
    orow[t + 256] = d1 * rs * g[t + 256] + be[t + 256];
    orow[t + 512] = d2 * rs * g[t + 512] + be[t + 512];
}

// ---------------- tiled GEMM: C = A[M,K] @ W[K,N] + bias, op: 0=store, 1=gelu, 2=residual add ----------------
#define GM 128
#define GN 64
#define GK 16
__global__ __launch_bounds__(256) void gemm_kernel(
    const float* __restrict__ A, const float* __restrict__ W,
    const float* __restrict__ bias, float* __restrict__ C,
    int M, int N, int K, int op)
{
    __shared__ float As[GK][GM + 4];
    __shared__ float Ws[GK][GN];
    int tid = threadIdx.x;
    int bm = blockIdx.y * GM, bn = blockIdx.x * GN;
    int ty = tid >> 4, tx = tid & 15;

    float acc[8][4];
    #pragma unroll
    for (int i = 0; i < 8; i++)
        #pragma unroll
        for (int j = 0; j < 4; j++) acc[i][j] = 0.0f;

    int aRow = tid >> 1;            // 0..127
    int aCol = (tid & 1) * 8;       // 0 or 8
    int wRow = tid >> 4;            // 0..15
    int wCol = (tid & 15) * 4;      // 0..60

    for (int k0 = 0; k0 < K; k0 += GK) {
        const float4* ap = (const float4*)(A + (size_t)(bm + aRow) * K + k0 + aCol);
        float4 a0 = ap[0], a1 = ap[1];
        As[aCol + 0][aRow] = a0.x; As[aCol + 1][aRow] = a0.y;
        As[aCol + 2][aRow] = a0.z; As[aCol + 3][aRow] = a0.w;
        As[aCol + 4][aRow] = a1.x; As[aCol + 5][aRow] = a1.y;
        As[aCol + 6][aRow] = a1.z; As[aCol + 7][aRow] = a1.w;
        float4 w4 = *(const float4*)(W + (size_t)(k0 + wRow) * N + bn + wCol);
        *(float4*)&Ws[wRow][wCol] = w4;
        __syncthreads();
        #pragma unroll
        for (int kk = 0; kk < GK; kk++) {
            float4 ra0 = *(const float4*)&As[kk][ty * 8];
            float4 ra1 = *(const float4*)&As[kk][ty * 8 + 4];
            float4 rw  = *(const float4*)&Ws[kk][tx * 4];
            float ar[8] = {ra0.x, ra0.y, ra0.z, ra0.w, ra1.x, ra1.y, ra1.z, ra1.w};
            float wr[4] = {rw.x, rw.y, rw.z, rw.w};
            #pragma unroll
            for (int i = 0; i < 8; i++)
                #pragma unroll
                for (int j = 0; j < 4; j++) acc[i][j] += ar[i] * wr[j];
        }
        __syncthreads();
    }
    #pragma unroll
    for (int i = 0; i < 8; i++) {
        int m = bm + ty * 8 + i;
        #pragma unroll
        for (int j = 0; j < 4; j++) {
            int n = bn + tx * 4 + j;
            float c = acc[i][j] + bias[n];
            if (op == 1) c = 0.5f * c * (1.0f + erff(c * 0.70710678118654752f));
            size_t idx = (size_t)m * N + n;
            if (op == 2) C[idx] += c;
            else         C[idx] = c;
        }
    }
}

// ---------------- fused attention: scores -> softmax (write attn) -> AV ----------------
#define QB 8
#define KC 64
__global__ __launch_bounds__(128) void attn_kernel(
    const float* __restrict__ Q, const float* __restrict__ K, const float* __restrict__ V,
    const int* __restrict__ mask, float* __restrict__ attn_out, float* __restrict__ ao)
{
    __shared__ float sQ[QB][DH];
    __shared__ float sS[QB][LL];
    __shared__ float sC[KC][DH + 1];
    __shared__ float red[128];

    int t  = threadIdx.x;
    int q0 = blockIdx.x * QB;
    int hh = blockIdx.y;
    int b  = blockIdx.z;

    // load Q rows
    for (int i = t; i < QB * DH; i += 128) {
        int qi = i >> 6, d = i & 63;
        sQ[qi][d] = Q[((size_t)(b * LL + q0 + qi)) * DD + hh * DH + d];
    }
    __syncthreads();

    // scores
    for (int kc = 0; kc < LL; kc += KC) {
        for (int i = t; i < KC * DH; i += 128) {
            int kk = i >> 6, d = i & 63;
            sC[kk][d] = K[((size_t)(b * LL + kc + kk)) * DD + hh * DH + d];
        }
        __syncthreads();
        #pragma unroll
        for (int j = 0; j < 4; j++) {
            int p = t + 128 * j;
            int qi = p >> 6;      // /64
            int kk = p & 63;
            float acc = 0.0f;
            #pragma unroll
            for (int d = 0; d < DH; d++) acc += sQ[qi][d] * sC[kk][d];
            int kg = kc + kk;
            float s = acc * 0.125f - 0.01f * (float)((q0 + qi) - kg);
            if (mask[b * LL + kg] == 0) s = -INFINITY;
            sS[qi][kg] = s;
        }
        __syncthreads();
    }

    // softmax per row + write attn to global
    for (int qi = 0; qi < QB; qi++) {
        float m = -1e30f;
        for (int k = t; k < LL; k += 128) m = fmaxf(m, sS[qi][k]);
        red[t] = m; __syncthreads();
        for (int o = 64; o > 0; o >>= 1) { if (t < o) red[t] = fmaxf(red[t], red[t + o]); __syncthreads(); }
        m = red[0]; __syncthreads();
        float ps = 0.0f;
        for (int k = t; k < LL; k += 128) {
            float e = expf(sS[qi][k] - m);
            sS[qi][k] = e;
            ps += e;
        }
        red[t] = ps; __syncthreads();
        for (int o = 64; o > 0; o >>= 1) { if (t < o) red[t] += red[t + o]; __syncthreads(); }
        float inv = 1.0f / red[0]; __syncthreads();
        size_t base = (((size_t)b * HH + hh) * LL + (q0 + qi)) * LL;
        for (int k = t; k < LL; k += 128) {
            float a = sS[qi][k] * inv;
            sS[qi][k] = a;
            attn_out[base + k] = a;
        }
    }
    __syncthreads();

    // AV: each thread computes 4 (qi, d) outputs
    int d  = t & 63;
    int qg = t >> 6;  // 0 or 1
    float acc[4] = {0.0f, 0.0f, 0.0f, 0.0f};
    for (int kc = 0; kc < LL; kc += KC) {
        for (int i = t; i < KC * DH; i += 128) {
            int kk = i >> 6, dd = i & 63;
            sC[kk][dd] = V[((size_t)(b * LL + kc + kk)) * DD + hh * DH + dd];
        }
        __syncthreads();
        #pragma unroll 8
        for (int kk = 0; kk < KC; kk++) {
            float v = sC[kk][d];
            #pragma unroll
            for (int j = 0; j < 4; j++) acc[j] += sS[qg * 4 + j][kc + kk] * v;
        }
        __syncthreads();
    }
    #pragma unroll
    for (int j = 0; j < 4; j++) {
        int qi = qg * 4 + j;
        ao[((size_t)(b * LL + q0 + qi)) * DD + hh * DH + d] = acc[j];
    }
}

// ---------------- classifier head: logits[b] = h[b,0,:] @ Wc + bc ----------------
__global__ void logits_kernel(const float* __restrict__ h, const float* __restrict__ Wc,
                              const float* __restrict__ bc, float* __restrict__ out) {
    __shared__ float red[256];
    int b = blockIdx.x;
    int t = threadIdx.x;
    float s = 0.0f;
    for (int d = t; d < DD; d += 256) s += h[(size_t)b * LL * DD + d] * Wc[d * NC];
    red[t] = s; __syncthreads();
    for (int o = 128; o > 0; o >>= 1) { if (t < o) red[t] += red[t + o]; __syncthreads(); }
    if (t == 0) out[b * NC] = red[0] + bc[0];
}

// ---------------- launcher ----------------
extern "C" void kernel_launch(void* const* d_in, const int* in_sizes, int n_in,
                              void* d_out, int out_size) {
    const int*   x    = (const int*)  d_in[0];
    const int*   mask = (const int*)  d_in[1];
    const float* emb  = (const float*)d_in[2];
    const float* Wq   = (const float*)d_in[3];
    const float* bq   = (const float*)d_in[4];
    const float* Wk   = (const float*)d_in[5];
    const float* bk   = (const float*)d_in[6];
    const float* Wv   = (const float*)d_in[7];
    const float* bv   = (const float*)d_in[8];
    const float* Wo   = (const float*)d_in[9];
    const float* bo   = (const float*)d_in[10];
    const float* W1   = (const float*)d_in[11];
    const float* b1   = (const float*)d_in[12];
    const float* W2   = (const float*)d_in[13];
    const float* b2   = (const float*)d_in[14];
    const float* g1   = (const float*)d_in[15];
    const float* be1  = (const float*)d_in[16];
    const float* g2   = (const float*)d_in[17];
    const float* be2  = (const float*)d_in[18];
    const float* Wc   = (const float*)d_in[19];
    const float* bc   = (const float*)d_in[20];

    float* out = (float*)d_out;
    float* logits = out;                          // [B, NC]
    float* attn_base = out + (size_t)BB * NC;     // [NL,B,H,L,L]

    float *p_h, *p_xn, *p_q, *p_k, *p_v, *p_ao, *p_ff;
    cudaGetSymbolAddress((void**)&p_h,  g_h);
    cudaGetSymbolAddress((void**)&p_xn, g_xn);
    cudaGetSymbolAddress((void**)&p_q,  g_q);
    cudaGetSymbolAddress((void**)&p_k,  g_k);
    cudaGetSymbolAddress((void**)&p_v,  g_v);
    cudaGetSymbolAddress((void**)&p_ao, g_ao);
    cudaGetSymbolAddress((void**)&p_ff, g_ff);

    embed_kernel<<<MM, 256>>>(x, emb, p_h);

    dim3 gD(DD / GN, MM / GM);   // N=768
    dim3 gF1(FF / GN, MM / GM);  // N=3072
    dim3 gAttn(LL / QB, HH, BB);

    for (int l = 0; l < NL; l++) {
        ln_kernel<<<MM, 256>>>(p_h, g1 + l * DD, be1 + l * DD, p_xn);
        gemm_kernel<<<gD, 256>>>(p_xn, Wq + (size_t)l * DD * DD, bq + l * DD, p_q, MM, DD, DD, 0);
        gemm_kernel<<<gD, 256>>>(p_xn, Wk + (size_t)l * DD * DD, bk + l * DD, p_k, MM, DD, DD, 0);
        gemm_kernel<<<gD, 256>>>(p_xn, Wv + (size_t)l * DD * DD, bv + l * DD, p_v, MM, DD, DD, 0);
        attn_kernel<<<gAttn, 128>>>(p_q, p_k, p_v, mask,
                                    attn_base + (size_t)l * BB * HH * LL * LL, p_ao);
        gemm_kernel<<<gD, 256>>>(p_ao, Wo + (size_t)l * DD * DD, bo + l * DD, p_h, MM, DD, DD, 2);
        ln_kernel<<<MM, 256>>>(p_h, g2 + l * DD, be2 + l * DD, p_xn);
        gemm_kernel<<<gF1, 256>>>(p_xn, W1 + (size_t)l * DD * FF, b1 + l * FF, p_ff, MM, FF, DD, 1);
        gemm_kernel<<<gD, 256>>>(p_ff, W2 + (size_t)l * FF * DD, b2 + l * DD, p_h, MM, DD, FF, 2);
    }

    logits_kernel<<<BB, 256>>>(p_h, Wc, bc, logits);
}

// round 3
// speedup vs baseline: 1.5671x; 1.5671x over previous
#include <cuda_runtime.h>
#include <cuda_bf16.h>
#include <math.h>
#include <stdint.h>

#define BB 8
#define LL 512
#define DD 768
#define HH 12
#define DH 64
#define FF 3072
#define NL 6
#define NC 1
#define MM (BB*LL)   // 4096

typedef __nv_bfloat16 bf16;

// ---------------- scratch ----------------
__device__ float g_h[MM*DD];
__device__ float g_q[MM*DD];
__device__ float g_k[MM*DD];
__device__ float g_v[MM*DD];
__device__ bf16 g_xnh[MM*DD], g_xnl[MM*DD];
__device__ bf16 g_aoh[MM*DD], g_aol[MM*DD];
__device__ bf16 g_ffh[MM*FF], g_ffl[MM*FF];
__device__ bf16 g_wqh[NL*DD*DD], g_wql[NL*DD*DD];
__device__ bf16 g_wkh[NL*DD*DD], g_wkl[NL*DD*DD];
__device__ bf16 g_wvh[NL*DD*DD], g_wvl[NL*DD*DD];
__device__ bf16 g_woh[NL*DD*DD], g_wol[NL*DD*DD];
__device__ bf16 g_w1h[NL*DD*FF], g_w1l[NL*DD*FF];
__device__ bf16 g_w2h[NL*FF*DD], g_w2l[NL*FF*DD];

// ---------------- PTX helpers (compute_103-safe: mma.sync / ldmatrix / cp.async) ----------------
__device__ __forceinline__ uint32_t smem_to_u32(const void* p) {
    uint32_t a;
    asm("{ .reg .u64 t; cvta.to.shared.u64 t, %1; cvt.u32.u64 %0, t; }" : "=r"(a) : "l"(p));
    return a;
}
__device__ __forceinline__ void cp_async16(uint32_t saddr, const void* gaddr) {
    asm volatile("cp.async.cg.shared.global [%0], [%1], 16;" :: "r"(saddr), "l"(gaddr) : "memory");
}
#define CP_COMMIT() asm volatile("cp.async.commit_group;" ::: "memory")
#define CP_WAIT1()  asm volatile("cp.async.wait_group 1;"  ::: "memory")
__device__ __forceinline__ void ldsm4(uint32_t* r, uint32_t a) {
    asm volatile("ldmatrix.sync.aligned.m8n8.x4.shared.b16 {%0,%1,%2,%3}, [%4];"
        : "=r"(r[0]), "=r"(r[1]), "=r"(r[2]), "=r"(r[3]) : "r"(a));
}
__device__ __forceinline__ void mma_bf16(float* c, const uint32_t* a, const uint32_t* b) {
    asm volatile("mma.sync.aligned.m16n8k16.row.col.f32.bf16.bf16.f32 "
        "{%0,%1,%2,%3}, {%4,%5,%6,%7}, {%8,%9}, {%0,%1,%2,%3};"
        : "+f"(c[0]), "+f"(c[1]), "+f"(c[2]), "+f"(c[3])
        : "r"(a[0]), "r"(a[1]), "r"(a[2]), "r"(a[3]), "r"(b[0]), "r"(b[1]));
}

// ---------------- weight transpose + bf16 split: W[K,N] -> Wt_hi/lo[N,K] ----------------
__global__ void tsplit_kernel(const float* __restrict__ W, bf16* __restrict__ Th,
                              bf16* __restrict__ Tl, int K, int N) {
    __shared__ float s[32][33];
    int l = blockIdx.z;
    const float* Wl = W + (size_t)l * K * N;
    bf16* Thl = Th + (size_t)l * K * N;
    bf16* Tll = Tl + (size_t)l * K * N;
    int n0 = blockIdx.x * 32, k0 = blockIdx.y * 32;
    int tx = threadIdx.x, ty = threadIdx.y;
    #pragma unroll
    for (int j = 0; j < 4; j++)
        s[ty + 8*j][tx] = Wl[(size_t)(k0 + ty + 8*j) * N + n0 + tx];
    __syncthreads();
    #pragma unroll
    for (int j = 0; j < 4; j++) {
        int row = ty + 8*j;
        float v = s[tx][row];
        bf16 hi = __float2bfloat16(v);
        bf16 lo = __float2bfloat16(v - __bfloat162float(hi));
        size_t idx = (size_t)(n0 + row) * K + k0 + tx;
        Thl[idx] = hi; Tll[idx] = lo;
    }
}

// ---------------- embedding + positional encoding ----------------
__global__ void embed_kernel(const int* __restrict__ x, const float* __restrict__ emb,
                             float* __restrict__ out) {
    int r = blockIdx.x;
    int b = r / LL;
    int tok = x[r];
    const float* erow = emb + (size_t)tok * DD;
    float* orow = out + (size_t)r * DD;
    const float neg_log = -logf(10000.0f) / (float)DD;
    for (int j = 0; j < 3; j++) {
        int d = threadIdx.x + j * 256;
        int i2 = (d >> 1) << 1;
        float div = expf((float)i2 * neg_log);
        float ang = (float)b * div;
        float pe = (d & 1) ? cosf(ang) : sinf(ang);
        orow[d] = erow[d] + pe;
    }
}

// ---------------- layernorm -> bf16 hi/lo ----------------
__global__ void ln_kernel(const float* __restrict__ in, const float* __restrict__ g,
                          const float* __restrict__ be,
                          bf16* __restrict__ oh, bf16* __restrict__ ol) {
    __shared__ float red[256];
    int r = blockIdx.x;
    int t = threadIdx.x;
    const float* xr = in + (size_t)r * DD;
    float v0 = xr[t], v1 = xr[t + 256], v2 = xr[t + 512];
    red[t] = v0 + v1 + v2;
    __syncthreads();
    for (int o = 128; o > 0; o >>= 1) { if (t < o) red[t] += red[t + o]; __syncthreads(); }
    float mean = red[0] * (1.0f / (float)DD);
    __syncthreads();
    float d0 = v0 - mean, d1 = v1 - mean, d2 = v2 - mean;
    red[t] = d0 * d0 + d1 * d1 + d2 * d2;
    __syncthreads();
    for (int o = 128; o > 0; o >>= 1) { if (t < o) red[t] += red[t + o]; __syncthreads(); }
    float var = red[0] * (1.0f / (float)DD);
    float rs = rsqrtf(var + 1e-5f);
    size_t base = (size_t)r * DD;
    float outs[3] = { d0 * rs * g[t] + be[t],
                      d1 * rs * g[t + 256] + be[t + 256],
                      d2 * rs * g[t + 512] + be[t + 512] };
    #pragma unroll
    for (int j = 0; j < 3; j++) {
        float v = outs[j];
        bf16 hi = __float2bfloat16(v);
        oh[base + t + 256*j] = hi;
        ol[base + t + 256*j] = __float2bfloat16(v - __bfloat162float(hi));
    }
}

// ---------------- HMMA GEMM: C[M,Ntot] = A[M,K] @ Wt[N,K]^T + bias ----------------
// 128x64x32 tiles, 8 warps (4m x 2n), 2-term bf16 split (3 MMAs / k-step)
// op: 0 = store fp32, 1 = GELU -> bf16 hi/lo, 2 = residual add fp32
#define STG_BYTES 30720
#define AL_OFF 10240
#define BH_OFF 20480
#define BL_OFF 25600
#define GEMM_SMEM (2*STG_BYTES)

__global__ __launch_bounds__(256) void gemm_mma(
    const bf16* __restrict__ Ah, const bf16* __restrict__ Al,
    const bf16* __restrict__ Bh, const bf16* __restrict__ Bl,
    const float* __restrict__ bias, float* __restrict__ C,
    bf16* __restrict__ Oh, bf16* __restrict__ Ol,
    int Ntot, int Ktot, int op)
{
    extern __shared__ char dsmem[];
    uint32_t smem_u = smem_to_u32(dsmem);
    int tid = threadIdx.x;
    int lane = tid & 31;
    int wid = tid >> 5;
    int wm = wid & 3;            // 0..3 (m)
    int wn = wid >> 2;           // 0..1 (n)
    int bm = blockIdx.y * 128, bn = blockIdx.x * 64;

    // ldmatrix per-lane byte offsets
    uint32_t a_off = (uint32_t)((wm*32 + (lane & 15)) * 80 + 16 * (lane >> 4));
    uint32_t b_off = (uint32_t)((wn*32 + 8*((lane >> 4) & 1) + (lane & 7)) * 80
                                + 16 * ((lane >> 3) & 1));

    // cp.async chunk mapping
    int arow0 = tid >> 2,        ac0 = (tid & 3);          // A chunks 0..255
    int arow1 = (tid + 256) >> 2, ac1 = ((tid + 256) & 3); // A chunks 256..511
    int brow  = tid >> 2,        bc  = (tid & 3);          // B chunks (64 rows)

    float acc[2][4][4];
    #pragma unroll
    for (int i = 0; i < 2; i++)
        #pragma unroll
        for (int j = 0; j < 4; j++)
            #pragma unroll
            for (int q = 0; q < 4; q++) acc[i][j][q] = 0.0f;

    int iters = Ktot >> 5;

    // stage loader
    #define LOAD_STAGE(it, buf) do { \
        int k0 = (it) << 5; \
        uint32_t sb = smem_u + (buf) * STG_BYTES; \
        cp_async16(sb + arow0*80 + ac0*16,           Ah + (size_t)(bm + arow0) * Ktot + k0 + ac0*8); \
        cp_async16(sb + AL_OFF + arow0*80 + ac0*16,  Al + (size_t)(bm + arow0) * Ktot + k0 + ac0*8); \
        cp_async16(sb + arow1*80 + ac1*16,           Ah + (size_t)(bm + arow1) * Ktot + k0 + ac1*8); \
        cp_async16(sb + AL_OFF + arow1*80 + ac1*16,  Al + (size_t)(bm + arow1) * Ktot + k0 + ac1*8); \
        cp_async16(sb + BH_OFF + brow*80 + bc*16,    Bh + (size_t)(bn + brow) * Ktot + k0 + bc*8); \
        cp_async16(sb + BL_OFF + brow*80 + bc*16,    Bl + (size_t)(bn + brow) * Ktot + k0 + bc*8); \
    } while (0)

    LOAD_STAGE(0, 0); CP_COMMIT();
    LOAD_STAGE(1, 1); CP_COMMIT();

    for (int it = 0; it < iters; it++) {
        CP_WAIT1();
        __syncthreads();
        int buf = it & 1;
        uint32_t sA  = smem_u + buf * STG_BYTES;
        uint32_t sAl = sA + AL_OFF;
        uint32_t sBh = sA + BH_OFF;
        uint32_t sBl = sA + BL_OFF;
        #pragma unroll
        for (int ks = 0; ks < 2; ks++) {
            uint32_t ah[2][4], al[2][4], bh[2][4], bl[2][4];
            #pragma unroll
            for (int tm = 0; tm < 2; tm++) {
                ldsm4(ah[tm], sA  + a_off + tm*1280 + ks*32);
                ldsm4(al[tm], sAl + a_off + tm*1280 + ks*32);
            }
            #pragma unroll
            for (int p = 0; p < 2; p++) {
                ldsm4(bh[p], sBh + b_off + p*1280 + ks*32);
                ldsm4(bl[p], sBl + b_off + p*1280 + ks*32);
            }
            #pragma unroll
            for (int tm = 0; tm < 2; tm++) {
                #pragma unroll
                for (int p = 0; p < 2; p++) {
                    mma_bf16(acc[tm][2*p],   ah[tm], &bh[p][0]);
                    mma_bf16(acc[tm][2*p],   ah[tm], &bl[p][0]);
                    mma_bf16(acc[tm][2*p],   al[tm], &bh[p][0]);
                    mma_bf16(acc[tm][2*p+1], ah[tm], &bh[p][2]);
                    mma_bf16(acc[tm][2*p+1], ah[tm], &bl[p][2]);
                    mma_bf16(acc[tm][2*p+1], al[tm], &bh[p][2]);
                }
            }
        }
        __syncthreads();
        if (it + 2 < iters) LOAD_STAGE(it + 2, buf);
        CP_COMMIT();
    }
    #undef LOAD_STAGE

    // epilogue
    int m_base = bm + wm*32 + (lane >> 2);
    int n_base = bn + wn*32 + (lane & 3)*2;
    #pragma unroll
    for (int tm = 0; tm < 2; tm++) {
        #pragma unroll
        for (int tn = 0; tn < 4; tn++) {
            #pragma unroll
            for (int half = 0; half < 2; half++) {
                int m = m_base + tm*16 + half*8;
                int n = n_base + tn*8;
                float v0 = acc[tm][tn][2*half]     + bias[n];
                float v1 = acc[tm][tn][2*half + 1] + bias[n + 1];
                size_t idx = (size_t)m * Ntot + n;
                if (op == 1) {
                    float gv0 = 0.5f * v0 * (1.0f + erff(v0 * 0.70710678118654752f));
                    float gv1 = 0.5f * v1 * (1.0f + erff(v1 * 0.70710678118654752f));
                    bf16 h0 = __float2bfloat16(gv0), h1 = __float2bfloat16(gv1);
                    Oh[idx] = h0; Oh[idx + 1] = h1;
                    Ol[idx]     = __float2bfloat16(gv0 - __bfloat162float(h0));
                    Ol[idx + 1] = __float2bfloat16(gv1 - __bfloat162float(h1));
                } else if (op == 2) {
                    C[idx]     += v0;
                    C[idx + 1] += v1;
                } else {
                    C[idx]     = v0;
                    C[idx + 1] = v1;
                }
            }
        }
    }
}

// ---------------- fused attention ----------------
#define QB 8
#define KC 64
__global__ __launch_bounds__(128) void attn_kernel(
    const float* __restrict__ Q, const float* __restrict__ K, const float* __restrict__ V,
    const int* __restrict__ mask, float* __restrict__ attn_out,
    bf16* __restrict__ aoh, bf16* __restrict__ aol)
{
    __shared__ float sQ[QB][DH];
    __shared__ float sS[QB][LL];
    __shared__ float sC[KC][DH + 1];
    __shared__ float red[128];

    int t  = threadIdx.x;
    int q0 = blockIdx.x * QB;
    int hh = blockIdx.y;
    int b  = blockIdx.z;

    for (int i = t; i < QB * DH; i += 128) {
        int qi = i >> 6, d = i & 63;
        sQ[qi][d] = Q[((size_t)(b * LL + q0 + qi)) * DD + hh * DH + d];
    }
    __syncthreads();

    for (int kc = 0; kc < LL; kc += KC) {
        for (int i = t; i < KC * DH; i += 128) {
            int kk = i >> 6, d = i & 63;
            sC[kk][d] = K[((size_t)(b * LL + kc + kk)) * DD + hh * DH + d];
        }
        __syncthreads();
        #pragma unroll
        for (int j = 0; j < 4; j++) {
            int p = t + 128 * j;
            int qi = p >> 6;
            int kk = p & 63;
            float accv = 0.0f;
            #pragma unroll
            for (int d = 0; d < DH; d++) accv += sQ[qi][d] * sC[kk][d];
            int kg = kc + kk;
            float s = accv * 0.125f - 0.01f * (float)((q0 + qi) - kg);
            if (mask[b * LL + kg] == 0) s = -INFINITY;
            sS[qi][kg] = s;
        }
        __syncthreads();
    }

    for (int qi = 0; qi < QB; qi++) {
        float m = -1e30f;
        for (int k = t; k < LL; k += 128) m = fmaxf(m, sS[qi][k]);
        red[t] = m; __syncthreads();
        for (int o = 64; o > 0; o >>= 1) { if (t < o) red[t] = fmaxf(red[t], red[t + o]); __syncthreads(); }
        m = red[0]; __syncthreads();
        float ps = 0.0f;
        for (int k = t; k < LL; k += 128) {
            float e = expf(sS[qi][k] - m);
            sS[qi][k] = e;
            ps += e;
        }
        red[t] = ps; __syncthreads();
        for (int o = 64; o > 0; o >>= 1) { if (t < o) red[t] += red[t + o]; __syncthreads(); }
        float inv = 1.0f / red[0]; __syncthreads();
        size_t base = (((size_t)b * HH + hh) * LL + (q0 + qi)) * LL;
        for (int k = t; k < LL; k += 128) {
            float a = sS[qi][k] * inv;
            sS[qi][k] = a;
            attn_out[base + k] = a;
        }
    }
    __syncthreads();

    int d  = t & 63;
    int qg = t >> 6;
    float accv[4] = {0.0f, 0.0f, 0.0f, 0.0f};
    for (int kc = 0; kc < LL; kc += KC) {
        for (int i = t; i < KC * DH; i += 128) {
            int kk = i >> 6, dd = i & 63;
            sC[kk][dd] = V[((size_t)(b * LL + kc + kk)) * DD + hh * DH + dd];
        }
        __syncthreads();
        #pragma unroll 8
        for (int kk = 0; kk < KC; kk++) {
            float v = sC[kk][d];
            #pragma unroll
            for (int j = 0; j < 4; j++) accv[j] += sS[qg * 4 + j][kc + kk] * v;
        }
        __syncthreads();
    }
    #pragma unroll
    for (int j = 0; j < 4; j++) {
        int qi = qg * 4 + j;
        size_t idx = ((size_t)(b * LL + q0 + qi)) * DD + hh * DH + d;
        float v = accv[j];
        bf16 hi = __float2bfloat16(v);
        aoh[idx] = hi;
        aol[idx] = __float2bfloat16(v - __bfloat162float(hi));
    }
}

// ---------------- classifier head ----------------
__global__ void logits_kernel(const float* __restrict__ h, const float* __restrict__ Wc,
                              const float* __restrict__ bc, float* __restrict__ out) {
    __shared__ float red[256];
    int b = blockIdx.x;
    int t = threadIdx.x;
    float s = 0.0f;
    for (int d = t; d < DD; d += 256) s += h[(size_t)b * LL * DD + d] * Wc[d * NC];
    red[t] = s; __syncthreads();
    for (int o = 128; o > 0; o >>= 1) { if (t < o) red[t] += red[t + o]; __syncthreads(); }
    if (t == 0) out[b * NC] = red[0] + bc[0];
}

// ---------------- launcher ----------------
extern "C" void kernel_launch(void* const* d_in, const int* in_sizes, int n_in,
                              void* d_out, int out_size) {
    const int*   x    = (const int*)  d_in[0];
    const int*   mask = (const int*)  d_in[1];
    const float* emb  = (const float*)d_in[2];
    const float* Wq   = (const float*)d_in[3];
    const float* bq   = (const float*)d_in[4];
    const float* Wk   = (const float*)d_in[5];
    const float* bk   = (const float*)d_in[6];
    const float* Wv   = (const float*)d_in[7];
    const float* bv   = (const float*)d_in[8];
    const float* Wo   = (const float*)d_in[9];
    const float* bo   = (const float*)d_in[10];
    const float* W1   = (const float*)d_in[11];
    const float* b1   = (const float*)d_in[12];
    const float* W2   = (const float*)d_in[13];
    const float* b2   = (const float*)d_in[14];
    const float* g1   = (const float*)d_in[15];
    const float* be1  = (const float*)d_in[16];
    const float* g2   = (const float*)d_in[17];
    const float* be2  = (const float*)d_in[18];
    const float* Wc   = (const float*)d_in[19];
    const float* bc   = (const float*)d_in[20];

    float* out = (float*)d_out;
    float* logits = out;
    float* attn_base = out + (size_t)BB * NC;

    static bool attr_set = false;
    if (!attr_set) {
        cudaFuncSetAttribute(gemm_mma, cudaFuncAttributeMaxDynamicSharedMemorySize, GEMM_SMEM);
        attr_set = true;
    }

    float *p_h, *p_q, *p_k, *p_v;
    bf16 *p_xnh, *p_xnl, *p_aoh, *p_aol, *p_ffh, *p_ffl;
    bf16 *p_wqh, *p_wql, *p_wkh, *p_wkl, *p_wvh, *p_wvl, *p_woh, *p_wol;
    bf16 *p_w1h, *p_w1l, *p_w2h, *p_w2l;
    cudaGetSymbolAddress((void**)&p_h, g_h);
    cudaGetSymbolAddress((void**)&p_q, g_q);
    cudaGetSymbolAddress((void**)&p_k, g_k);
    cudaGetSymbolAddress((void**)&p_v, g_v);
    cudaGetSymbolAddress((void**)&p_xnh, g_xnh); cudaGetSymbolAddress((void**)&p_xnl, g_xnl);
    cudaGetSymbolAddress((void**)&p_aoh, g_aoh); cudaGetSymbolAddress((void**)&p_aol, g_aol);
    cudaGetSymbolAddress((void**)&p_ffh, g_ffh); cudaGetSymbolAddress((void**)&p_ffl, g_ffl);
    cudaGetSymbolAddress((void**)&p_wqh, g_wqh); cudaGetSymbolAddress((void**)&p_wql, g_wql);
    cudaGetSymbolAddress((void**)&p_wkh, g_wkh); cudaGetSymbolAddress((void**)&p_wkl, g_wkl);
    cudaGetSymbolAddress((void**)&p_wvh, g_wvh); cudaGetSymbolAddress((void**)&p_wvl, g_wvl);
    cudaGetSymbolAddress((void**)&p_woh, g_woh); cudaGetSymbolAddress((void**)&p_wol, g_wol);
    cudaGetSymbolAddress((void**)&p_w1h, g_w1h); cudaGetSymbolAddress((void**)&p_w1l, g_w1l);
    cudaGetSymbolAddress((void**)&p_w2h, g_w2h); cudaGetSymbolAddress((void**)&p_w2l, g_w2l);

    dim3 tb(32, 8);
    tsplit_kernel<<<dim3(DD/32, DD/32, NL), tb>>>(Wq, p_wqh, p_wql, DD, DD);
    tsplit_kernel<<<dim3(DD/32, DD/32, NL), tb>>>(Wk, p_wkh, p_wkl, DD, DD);
    tsplit_kernel<<<dim3(DD/32, DD/32, NL), tb>>>(Wv, p_wvh, p_wvl, DD, DD);
    tsplit_kernel<<<dim3(DD/32, DD/32, NL), tb>>>(Wo, p_woh, p_wol, DD, DD);
    tsplit_kernel<<<dim3(FF/32, DD/32, NL), tb>>>(W1, p_w1h, p_w1l, DD, FF);
    tsplit_kernel<<<dim3(DD/32, FF/32, NL), tb>>>(W2, p_w2h, p_w2l, FF, DD);

    embed_kernel<<<MM, 256>>>(x, emb, p_h);

    dim3 gD(DD/64, MM/128);    // N=768
    dim3 gF(FF/64, MM/128);    // N=3072
    dim3 gAttn(LL/QB, HH, BB);

    for (int l = 0; l < NL; l++) {
        size_t wD = (size_t)l * DD * DD;
        size_t wF = (size_t)l * DD * FF;
        ln_kernel<<<MM, 256>>>(p_h, g1 + l*DD, be1 + l*DD, p_xnh, p_xnl);
        gemm_mma<<<gD, 256, GEMM_SMEM>>>(p_xnh, p_xnl, p_wqh + wD, p_wql + wD, bq + l*DD, p_q, nullptr, nullptr, DD, DD, 0);
        gemm_mma<<<gD, 256, GEMM_SMEM>>>(p_xnh, p_xnl, p_wkh + wD, p_wkl + wD, bk + l*DD, p_k, nullptr, nullptr, DD, DD, 0);
        gemm_mma<<<gD, 256, GEMM_SMEM>>>(p_xnh, p_xnl, p_wvh + wD, p_wvl + wD, bv + l*DD, p_v, nullptr, nullptr, DD, DD, 0);
        attn_kernel<<<gAttn, 128>>>(p_q, p_k, p_v, mask,
                                    attn_base + (size_t)l * BB * HH * LL * LL, p_aoh, p_aol);
        gemm_mma<<<gD, 256, GEMM_SMEM>>>(p_aoh, p_aol, p_woh + wD, p_wol + wD, bo + l*DD, p_h, nullptr, nullptr, DD, DD, 2);
        ln_kernel<<<MM, 256>>>(p_h, g2 + l*DD, be2 + l*DD, p_xnh, p_xnl);
        gemm_mma<<<gF, 256, GEMM_SMEM>>>(p_xnh, p_xnl, p_w1h + wF, p_w1l + wF, b1 + l*FF, nullptr, p_ffh, p_ffl, FF, DD, 1);
        gemm_mma<<<gD, 256, GEMM_SMEM>>>(p_ffh, p_ffl, p_w2h + wF, p_w2l + wF, b2 + l*DD, p_h, nullptr, nullptr, DD, FF, 2);
    }

    logits_kernel<<<BB, 256>>>(p_h, Wc, bc, logits);
}

// round 4
// speedup vs baseline: 2.7915x; 1.7814x over previous
#include <cuda_runtime.h>
#include <cuda_bf16.h>
#include <math.h>
#include <stdint.h>

#define BB 8
#define LL 512
#define DD 768
#define HH 12
#define DH 64
#define FF 3072
#define NL 6
#define NC 1
#define MM (BB*LL)   // 4096
#define NQKV 2304

typedef __nv_bfloat16 bf16;

// ---------------- scratch ----------------
__device__ float g_h[MM*DD];
__device__ bf16 g_xnh[MM*DD], g_xnl[MM*DD];
__device__ bf16 g_qkvh[MM*NQKV], g_qkvl[MM*NQKV];
__device__ bf16 g_aoh[MM*DD], g_aol[MM*DD];
__device__ bf16 g_ffh[MM*FF], g_ffl[MM*FF];
__device__ bf16 g_wqkvh[NL*NQKV*DD], g_wqkvl[NL*NQKV*DD];
__device__ bf16 g_woh[NL*DD*DD], g_wol[NL*DD*DD];
__device__ bf16 g_w1h[NL*DD*FF], g_w1l[NL*DD*FF];
__device__ bf16 g_w2h[NL*FF*DD], g_w2l[NL*FF*DD];
__device__ float g_bqkv[NL*NQKV];

// ---------------- PTX helpers ----------------
__device__ __forceinline__ uint32_t smem_to_u32(const void* p) {
    uint32_t a;
    asm("{ .reg .u64 t; cvta.to.shared.u64 t, %1; cvt.u32.u64 %0, t; }" : "=r"(a) : "l"(p));
    return a;
}
__device__ __forceinline__ void cp_async16(uint32_t saddr, const void* gaddr) {
    asm volatile("cp.async.cg.shared.global [%0], [%1], 16;" :: "r"(saddr), "l"(gaddr) : "memory");
}
#define CP_COMMIT() asm volatile("cp.async.commit_group;" ::: "memory")
#define CP_WAIT1()  asm volatile("cp.async.wait_group 1;"  ::: "memory")
__device__ __forceinline__ void ldsm4(uint32_t* r, uint32_t a) {
    asm volatile("ldmatrix.sync.aligned.m8n8.x4.shared.b16 {%0,%1,%2,%3}, [%4];"
        : "=r"(r[0]), "=r"(r[1]), "=r"(r[2]), "=r"(r[3]) : "r"(a));
}
__device__ __forceinline__ void ldsm4t(uint32_t* r, uint32_t a) {
    asm volatile("ldmatrix.sync.aligned.m8n8.x4.trans.shared.b16 {%0,%1,%2,%3}, [%4];"
        : "=r"(r[0]), "=r"(r[1]), "=r"(r[2]), "=r"(r[3]) : "r"(a));
}
__device__ __forceinline__ void mma_bf16(float* c, const uint32_t* a, const uint32_t* b) {
    asm volatile("mma.sync.aligned.m16n8k16.row.col.f32.bf16.bf16.f32 "
        "{%0,%1,%2,%3}, {%4,%5,%6,%7}, {%8,%9}, {%0,%1,%2,%3};"
        : "+f"(c[0]), "+f"(c[1]), "+f"(c[2]), "+f"(c[3])
        : "r"(a[0]), "r"(a[1]), "r"(a[2]), "r"(a[3]), "r"(b[0]), "r"(b[1]));
}
__device__ __forceinline__ uint32_t packbb(bf16 a, bf16 b) {
    __nv_bfloat162 t; t.x = a; t.y = b; return *(uint32_t*)&t;
}

// ---------------- weight transpose + bf16 split ----------------
__global__ void tsplit_kernel(const float* __restrict__ W, bf16* __restrict__ Th,
                              bf16* __restrict__ Tl, int K, int N,
                              int roff, size_t out_ls) {
    __shared__ float s[32][33];
    int l = blockIdx.z;
    const float* Wl = W + (size_t)l * K * N;
    bf16* Thl = Th + (size_t)l * out_ls;
    bf16* Tll = Tl + (size_t)l * out_ls;
    int n0 = blockIdx.x * 32, k0 = blockIdx.y * 32;
    int tx = threadIdx.x, ty = threadIdx.y;
    #pragma unroll
    for (int j = 0; j < 4; j++)
        s[ty + 8*j][tx] = Wl[(size_t)(k0 + ty + 8*j) * N + n0 + tx];
    __syncthreads();
    #pragma unroll
    for (int j = 0; j < 4; j++) {
        int row = ty + 8*j;
        float v = s[tx][row];
        bf16 hi = __float2bfloat16(v);
        bf16 lo = __float2bfloat16(v - __bfloat162float(hi));
        size_t idx = (size_t)(roff + n0 + row) * K + k0 + tx;
        Thl[idx] = hi; Tll[idx] = lo;
    }
}

__global__ void bias_concat(const float* __restrict__ bq, const float* __restrict__ bk,
                            const float* __restrict__ bv, float* __restrict__ o) {
    int l = blockIdx.y;
    int j = blockIdx.x * 256 + threadIdx.x;
    float v = (j < 768) ? bq[l*768 + j] : (j < 1536) ? bk[l*768 + j - 768] : bv[l*768 + j - 1536];
    o[l*NQKV + j] = v;
}

// ---------------- embedding + positional encoding ----------------
__global__ void embed_kernel(const int* __restrict__ x, const float* __restrict__ emb,
                             float* __restrict__ out) {
    int r = blockIdx.x;
    int b = r / LL;
    int tok = x[r];
    const float* erow = emb + (size_t)tok * DD;
    float* orow = out + (size_t)r * DD;
    const float neg_log = -logf(10000.0f) / (float)DD;
    for (int j = 0; j < 3; j++) {
        int d = threadIdx.x + j * 256;
        int i2 = (d >> 1) << 1;
        float div = expf((float)i2 * neg_log);
        float ang = (float)b * div;
        float pe = (d & 1) ? cosf(ang) : sinf(ang);
        orow[d] = erow[d] + pe;
    }
}

// ---------------- layernorm -> bf16 hi/lo ----------------
__global__ void ln_kernel(const float* __restrict__ in, const float* __restrict__ g,
                          const float* __restrict__ be,
                          bf16* __restrict__ oh, bf16* __restrict__ ol) {
    __shared__ float red[256];
    int r = blockIdx.x;
    int t = threadIdx.x;
    const float* xr = in + (size_t)r * DD;
    float v0 = xr[t], v1 = xr[t + 256], v2 = xr[t + 512];
    red[t] = v0 + v1 + v2;
    __syncthreads();
    for (int o = 128; o > 0; o >>= 1) { if (t < o) red[t] += red[t + o]; __syncthreads(); }
    float mean = red[0] * (1.0f / (float)DD);
    __syncthreads();
    float d0 = v0 - mean, d1 = v1 - mean, d2 = v2 - mean;
    red[t] = d0 * d0 + d1 * d1 + d2 * d2;
    __syncthreads();
    for (int o = 128; o > 0; o >>= 1) { if (t < o) red[t] += red[t + o]; __syncthreads(); }
    float var = red[0] * (1.0f / (float)DD);
    float rs = rsqrtf(var + 1e-5f);
    size_t base = (size_t)r * DD;
    float outs[3] = { d0 * rs * g[t] + be[t],
                      d1 * rs * g[t + 256] + be[t + 256],
                      d2 * rs * g[t + 512] + be[t + 512] };
    #pragma unroll
    for (int j = 0; j < 3; j++) {
        float v = outs[j];
        bf16 hi = __float2bfloat16(v);
        oh[base + t + 256*j] = hi;
        ol[base + t + 256*j] = __float2bfloat16(v - __bfloat162float(hi));
    }
}

// ---------------- HMMA GEMM ----------------
// op: 0 = store fp32, 1 = GELU -> bf16 hi/lo, 2 = residual add fp32, 3 = store bf16 hi/lo
#define STG_BYTES 30720
#define AL_OFF 10240
#define BH_OFF 20480
#define BL_OFF 25600
#define GEMM_SMEM (2*STG_BYTES)

__global__ __launch_bounds__(256) void gemm_mma(
    const bf16* __restrict__ Ah, const bf16* __restrict__ Al,
    const bf16* __restrict__ Bh, const bf16* __restrict__ Bl,
    const float* __restrict__ bias, float* __restrict__ C,
    bf16* __restrict__ Oh, bf16* __restrict__ Ol,
    int Ntot, int Ktot, int op)
{
    extern __shared__ char dsmem[];
    uint32_t smem_u = smem_to_u32(dsmem);
    int tid = threadIdx.x;
    int lane = tid & 31;
    int wid = tid >> 5;
    int wm = wid & 3;
    int wn = wid >> 2;
    int bm = blockIdx.y * 128, bn = blockIdx.x * 64;

    uint32_t a_off = (uint32_t)((wm*32 + (lane & 15)) * 80 + 16 * (lane >> 4));
    uint32_t b_off = (uint32_t)((wn*32 + 8*((lane >> 4) & 1) + (lane & 7)) * 80
                                + 16 * ((lane >> 3) & 1));

    int arow0 = tid >> 2,         ac0 = (tid & 3);
    int arow1 = (tid + 256) >> 2, ac1 = ((tid + 256) & 3);
    int brow  = tid >> 2,         bc  = (tid & 3);

    float acc[2][4][4];
    #pragma unroll
    for (int i = 0; i < 2; i++)
        #pragma unroll
        for (int j = 0; j < 4; j++)
            #pragma unroll
            for (int q = 0; q < 4; q++) acc[i][j][q] = 0.0f;

    int iters = Ktot >> 5;

    #define LOAD_STAGE(it, buf) do { \
        int k0 = (it) << 5; \
        uint32_t sb = smem_u + (buf) * STG_BYTES; \
        cp_async16(sb + arow0*80 + ac0*16,           Ah + (size_t)(bm + arow0) * Ktot + k0 + ac0*8); \
        cp_async16(sb + AL_OFF + arow0*80 + ac0*16,  Al + (size_t)(bm + arow0) * Ktot + k0 + ac0*8); \
        cp_async16(sb + arow1*80 + ac1*16,           Ah + (size_t)(bm + arow1) * Ktot + k0 + ac1*8); \
        cp_async16(sb + AL_OFF + arow1*80 + ac1*16,  Al + (size_t)(bm + arow1) * Ktot + k0 + ac1*8); \
        cp_async16(sb + BH_OFF + brow*80 + bc*16,    Bh + (size_t)(bn + brow) * Ktot + k0 + bc*8); \
        cp_async16(sb + BL_OFF + brow*80 + bc*16,    Bl + (size_t)(bn + brow) * Ktot + k0 + bc*8); \
    } while (0)

    LOAD_STAGE(0, 0); CP_COMMIT();
    LOAD_STAGE(1, 1); CP_COMMIT();

    for (int it = 0; it < iters; it++) {
        CP_WAIT1();
        __syncthreads();
        int buf = it & 1;
        uint32_t sA  = smem_u + buf * STG_BYTES;
        uint32_t sAl = sA + AL_OFF;
        uint32_t sBh = sA + BH_OFF;
        uint32_t sBl = sA + BL_OFF;
        #pragma unroll
        for (int ks = 0; ks < 2; ks++) {
            uint32_t ah[2][4], al[2][4], bh[2][4], bl[2][4];
            #pragma unroll
            for (int tm = 0; tm < 2; tm++) {
                ldsm4(ah[tm], sA  + a_off + tm*1280 + ks*32);
                ldsm4(al[tm], sAl + a_off + tm*1280 + ks*32);
            }
            #pragma unroll
            for (int p = 0; p < 2; p++) {
                ldsm4(bh[p], sBh + b_off + p*1280 + ks*32);
                ldsm4(bl[p], sBl + b_off + p*1280 + ks*32);
            }
            // pass 1: Ah*Bh  (8 independent accumulators per pass)
            #pragma unroll
            for (int tm = 0; tm < 2; tm++)
                #pragma unroll
                for (int p = 0; p < 2; p++) {
                    mma_bf16(acc[tm][2*p],   ah[tm], &bh[p][0]);
                    mma_bf16(acc[tm][2*p+1], ah[tm], &bh[p][2]);
                }
            // pass 2: Ah*Bl
            #pragma unroll
            for (int tm = 0; tm < 2; tm++)
                #pragma unroll
                for (int p = 0; p < 2; p++) {
                    mma_bf16(acc[tm][2*p],   ah[tm], &bl[p][0]);
                    mma_bf16(acc[tm][2*p+1], ah[tm], &bl[p][2]);
                }
            // pass 3: Al*Bh
            #pragma unroll
            for (int tm = 0; tm < 2; tm++)
                #pragma unroll
                for (int p = 0; p < 2; p++) {
                    mma_bf16(acc[tm][2*p],   al[tm], &bh[p][0]);
                    mma_bf16(acc[tm][2*p+1], al[tm], &bh[p][2]);
                }
        }
        __syncthreads();
        if (it + 2 < iters) LOAD_STAGE(it + 2, buf);
        CP_COMMIT();
    }
    #undef LOAD_STAGE

    int m_base = bm + wm*32 + (lane >> 2);
    int n_base = bn + wn*32 + (lane & 3)*2;
    #pragma unroll
    for (int tm = 0; tm < 2; tm++) {
        #pragma unroll
        for (int tn = 0; tn < 4; tn++) {
            #pragma unroll
            for (int half = 0; half < 2; half++) {
                int m = m_base + tm*16 + half*8;
                int n = n_base + tn*8;
                float v0 = acc[tm][tn][2*half]     + bias[n];
                float v1 = acc[tm][tn][2*half + 1] + bias[n + 1];
                size_t idx = (size_t)m * Ntot + n;
                if (op == 1) {
                    float gv0 = 0.5f * v0 * (1.0f + erff(v0 * 0.70710678118654752f));
                    float gv1 = 0.5f * v1 * (1.0f + erff(v1 * 0.70710678118654752f));
                    bf16 h0 = __float2bfloat16(gv0), h1 = __float2bfloat16(gv1);
                    *(uint32_t*)(Oh + idx) = packbb(h0, h1);
                    *(uint32_t*)(Ol + idx) = packbb(
                        __float2bfloat16(gv0 - __bfloat162float(h0)),
                        __float2bfloat16(gv1 - __bfloat162float(h1)));
                } else if (op == 2) {
                    C[idx]     += v0;
                    C[idx + 1] += v1;
                } else if (op == 3) {
                    bf16 h0 = __float2bfloat16(v0), h1 = __float2bfloat16(v1);
                    *(uint32_t*)(Oh + idx) = packbb(h0, h1);
                    *(uint32_t*)(Ol + idx) = packbb(
                        __float2bfloat16(v0 - __bfloat162float(h0)),
                        __float2bfloat16(v1 - __bfloat162float(h1)));
                } else {
                    C[idx]     = v0;
                    C[idx + 1] = v1;
                }
            }
        }
    }
}

// ---------------- tensor-core fused attention ----------------
// block = (qtile 64, head, batch). S[64][512] fp32 in smem.
#define SSTR 520
#define OFF_Q  (64*SSTR*4)        // 133120
#define OFF_QL (OFF_Q + 9216)
#define OFF_K  (OFF_QL + 9216)    // 151552
#define OFF_KL (OFF_K + 18432)
#define ATTN_SMEM (OFF_KL + 18432) // 188416

__global__ __launch_bounds__(256) void attn_tc(
    const bf16* __restrict__ QKVh, const bf16* __restrict__ QKVl,
    const int* __restrict__ mask, float* __restrict__ attn_out,
    bf16* __restrict__ aoh, bf16* __restrict__ aol)
{
    extern __shared__ char sm[];
    float* S = (float*)sm;
    uint32_t su = smem_to_u32(sm);
    int tid = threadIdx.x, lane = tid & 31, wid = tid >> 5;
    int q0 = blockIdx.x * 64;
    int h = blockIdx.y, b = blockIdx.z;

    // load Q tile (64 rows x 64 bf16, hi/lo)
    {
        int r = tid >> 2, c = tid & 3;
        size_t g = ((size_t)(b*LL + q0 + r)) * NQKV + h*DH;
        const uint4* gh = (const uint4*)(QKVh + g);
        const uint4* gl = (const uint4*)(QKVl + g);
        *(uint4*)(sm + OFF_Q  + r*144 + c*16)     = gh[c];
        *(uint4*)(sm + OFF_Q  + r*144 + (c+4)*16) = gh[c+4];
        *(uint4*)(sm + OFF_QL + r*144 + c*16)     = gl[c];
        *(uint4*)(sm + OFF_QL + r*144 + (c+4)*16) = gl[c+4];
    }

    int wm = wid & 1, wn = wid >> 1;

    // ---- scores: S = scale*QK^T + bias + mask ----
    for (int kc = 0; kc < 4; kc++) {
        {
            int r = tid >> 1, c0 = (tid & 1) * 4;
            size_t g = ((size_t)(b*LL + kc*128 + r)) * NQKV + 768 + h*DH;
            const uint4* gh = (const uint4*)(QKVh + g);
            const uint4* gl = (const uint4*)(QKVl + g);
            #pragma unroll
            for (int c = 0; c < 4; c++) {
                *(uint4*)(sm + OFF_K  + r*144 + (c0+c)*16) = gh[c0+c];
                *(uint4*)(sm + OFF_KL + r*144 + (c0+c)*16) = gl[c0+c];
            }
        }
        __syncthreads();
        float acc[2][4][4];
        #pragma unroll
        for (int i = 0; i < 2; i++)
            #pragma unroll
            for (int j = 0; j < 4; j++)
                #pragma unroll
                for (int q = 0; q < 4; q++) acc[i][j][q] = 0.0f;
        uint32_t aoff = (uint32_t)((wm*32 + (lane & 15)) * 144 + 16 * (lane >> 4));
        uint32_t boff = (uint32_t)((wn*32 + 8*((lane >> 4) & 1) + (lane & 7)) * 144
                                   + 16 * ((lane >> 3) & 1));
        #pragma unroll
        for (int ki = 0; ki < 4; ki++) {
            uint32_t ah[2][4], al[2][4], bh[2][4], bl[2][4];
            #pragma unroll
            for (int tm = 0; tm < 2; tm++) {
                ldsm4(ah[tm], su + OFF_Q  + aoff + tm*2304 + ki*32);
                ldsm4(al[tm], su + OFF_QL + aoff + tm*2304 + ki*32);
            }
            #pragma unroll
            for (int p = 0; p < 2; p++) {
                ldsm4(bh[p], su + OFF_K  + boff + p*2304 + ki*32);
                ldsm4(bl[p], su + OFF_KL + boff + p*2304 + ki*32);
            }
            #pragma unroll
            for (int tm = 0; tm < 2; tm++)
                #pragma unroll
                for (int p = 0; p < 2; p++) {
                    mma_bf16(acc[tm][2*p],   ah[tm], &bh[p][0]);
                    mma_bf16(acc[tm][2*p+1], ah[tm], &bh[p][2]);
                }
            #pragma unroll
            for (int tm = 0; tm < 2; tm++)
                #pragma unroll
                for (int p = 0; p < 2; p++) {
                    mma_bf16(acc[tm][2*p],   ah[tm], &bl[p][0]);
                    mma_bf16(acc[tm][2*p+1], ah[tm], &bl[p][2]);
                }
            #pragma unroll
            for (int tm = 0; tm < 2; tm++)
                #pragma unroll
                for (int p = 0; p < 2; p++) {
                    mma_bf16(acc[tm][2*p],   al[tm], &bh[p][0]);
                    mma_bf16(acc[tm][2*p+1], al[tm], &bh[p][2]);
                }
        }
        // epilogue: scale + bias + mask -> S
        #pragma unroll
        for (int tm = 0; tm < 2; tm++) {
            #pragma unroll
            for (int tn = 0; tn < 4; tn++) {
                int row = wm*32 + tm*16 + (lane >> 2);
                int col = kc*128 + wn*32 + tn*8 + (lane & 3)*2;
                int m0 = mask[b*LL + col], m1 = mask[b*LL + col + 1];
                #pragma unroll
                for (int half = 0; half < 2; half++) {
                    int rr = row + half*8;
                    float v0 = acc[tm][tn][2*half]   * 0.125f - 0.01f * (float)((q0 + rr) - col);
                    float v1 = acc[tm][tn][2*half+1] * 0.125f - 0.01f * (float)((q0 + rr) - (col+1));
                    if (m0 == 0) v0 = -INFINITY;
                    if (m1 == 0) v1 = -INFINITY;
                    S[rr*SSTR + col]     = v0;
                    S[rr*SSTR + col + 1] = v1;
                }
            }
        }
        __syncthreads();
    }

    // ---- softmax (one warp per row, 8 rows each) + P writeout ----
    {
        size_t gbase0 = ((size_t)(b*HH + h) * LL + q0) * LL;
        #pragma unroll
        for (int j = 0; j < 8; j++) {
            int r = wid*8 + j;
            float4 e[4];
            #pragma unroll
            for (int i = 0; i < 4; i++) e[i] = *(float4*)&S[r*SSTR + i*128 + lane*4];
            float mx = -1e30f;
            #pragma unroll
            for (int i = 0; i < 4; i++) {
                mx = fmaxf(mx, fmaxf(fmaxf(e[i].x, e[i].y), fmaxf(e[i].z, e[i].w)));
            }
            #pragma unroll
            for (int o = 16; o > 0; o >>= 1) mx = fmaxf(mx, __shfl_xor_sync(0xFFFFFFFFu, mx, o));
            float sum = 0.0f;
            #pragma unroll
            for (int i = 0; i < 4; i++) {
                e[i].x = __expf(e[i].x - mx); e[i].y = __expf(e[i].y - mx);
                e[i].z = __expf(e[i].z - mx); e[i].w = __expf(e[i].w - mx);
                sum += e[i].x + e[i].y + e[i].z + e[i].w;
            }
            #pragma unroll
            for (int o = 16; o > 0; o >>= 1) sum += __shfl_xor_sync(0xFFFFFFFFu, sum, o);
            float inv = 1.0f / sum;
            float* gp = attn_out + gbase0 + (size_t)r * LL;
            #pragma unroll
            for (int i = 0; i < 4; i++) {
                e[i].x *= inv; e[i].y *= inv; e[i].z *= inv; e[i].w *= inv;
                *(float4*)&S[r*SSTR + i*128 + lane*4] = e[i];
                *(float4*)(gp + i*128 + lane*4) = e[i];
            }
        }
    }
    __syncthreads();

    // ---- AV: O = P @ V ----
    float oa[2][2][4];
    #pragma unroll
    for (int i = 0; i < 2; i++)
        #pragma unroll
        for (int j = 0; j < 2; j++)
            #pragma unroll
            for (int q = 0; q < 4; q++) oa[i][j][q] = 0.0f;

    for (int kc = 0; kc < 8; kc++) {
        // convert P chunk (fp32 -> bf16 hi/lo) into Q area
        {
            int r = tid >> 2, c0 = (tid & 3) * 16;
            #pragma unroll
            for (int jj = 0; jj < 2; jj++) {
                const float* sp = &S[r*SSTR + kc*64 + c0 + jj*8];
                float v[8];
                *(float4*)&v[0] = *(const float4*)sp;
                *(float4*)&v[4] = *(const float4*)(sp + 4);
                uint32_t hw[4], lw[4];
                #pragma unroll
                for (int q = 0; q < 4; q++) {
                    bf16 ha = __float2bfloat16(v[2*q]), hb = __float2bfloat16(v[2*q+1]);
                    hw[q] = packbb(ha, hb);
                    lw[q] = packbb(__float2bfloat16(v[2*q]   - __bfloat162float(ha)),
                                   __float2bfloat16(v[2*q+1] - __bfloat162float(hb)));
                }
                *(uint4*)(sm + OFF_Q  + r*144 + (c0 + jj*8)*2) = *(uint4*)hw;
                *(uint4*)(sm + OFF_QL + r*144 + (c0 + jj*8)*2) = *(uint4*)lw;
            }
        }
        // load V chunk (64 k-rows) into K area
        {
            int r = tid >> 2, c = tid & 3;
            size_t g = ((size_t)(b*LL + kc*64 + r)) * NQKV + 1536 + h*DH;
            const uint4* gh = (const uint4*)(QKVh + g);
            const uint4* gl = (const uint4*)(QKVl + g);
            *(uint4*)(sm + OFF_K  + r*144 + c*16)     = gh[c];
            *(uint4*)(sm + OFF_K  + r*144 + (c+4)*16) = gh[c+4];
            *(uint4*)(sm + OFF_KL + r*144 + c*16)     = gl[c];
            *(uint4*)(sm + OFF_KL + r*144 + (c+4)*16) = gl[c+4];
        }
        __syncthreads();
        uint32_t poff = (uint32_t)((wm*32 + (lane & 15)) * 144 + 16 * (lane >> 4));
        uint32_t voff = (uint32_t)((lane & 15) * 144 + wn*32 + 16 * (lane >> 4));
        #pragma unroll
        for (int ki = 0; ki < 4; ki++) {
            uint32_t ph[2][4], pl[2][4], vh[4], vl[4];
            #pragma unroll
            for (int tm = 0; tm < 2; tm++) {
                ldsm4(ph[tm], su + OFF_Q  + poff + tm*2304 + ki*32);
                ldsm4(pl[tm], su + OFF_QL + poff + tm*2304 + ki*32);
            }
            ldsm4t(vh, su + OFF_K  + voff + ki*2304);
            ldsm4t(vl, su + OFF_KL + voff + ki*2304);
            #pragma unroll
            for (int tm = 0; tm < 2; tm++)
                #pragma unroll
                for (int tn = 0; tn < 2; tn++)
                    mma_bf16(oa[tm][tn], ph[tm], &vh[2*tn]);
            #pragma unroll
            for (int tm = 0; tm < 2; tm++)
                #pragma unroll
                for (int tn = 0; tn < 2; tn++)
                    mma_bf16(oa[tm][tn], ph[tm], &vl[2*tn]);
            #pragma unroll
            for (int tm = 0; tm < 2; tm++)
                #pragma unroll
                for (int tn = 0; tn < 2; tn++)
                    mma_bf16(oa[tm][tn], pl[tm], &vh[2*tn]);
        }
        __syncthreads();
    }

    // O epilogue -> bf16 hi/lo for Wo GEMM
    #pragma unroll
    for (int tm = 0; tm < 2; tm++) {
        #pragma unroll
        for (int tn = 0; tn < 2; tn++) {
            #pragma unroll
            for (int half = 0; half < 2; half++) {
                int row = wm*32 + tm*16 + (lane >> 2) + half*8;
                int col = wn*16 + tn*8 + (lane & 3)*2;
                float v0 = oa[tm][tn][2*half], v1 = oa[tm][tn][2*half+1];
                size_t g = ((size_t)(b*LL + q0 + row)) * DD + h*DH + col;
                bf16 h0 = __float2bfloat16(v0), h1 = __float2bfloat16(v1);
                *(uint32_t*)(aoh + g) = packbb(h0, h1);
                *(uint32_t*)(aol + g) = packbb(
                    __float2bfloat16(v0 - __bfloat162float(h0)),
                    __float2bfloat16(v1 - __bfloat162float(h1)));
            }
        }
    }
}

// ---------------- classifier head ----------------
__global__ void logits_kernel(const float* __restrict__ h, const float* __restrict__ Wc,
                              const float* __restrict__ bc, float* __restrict__ out) {
    __shared__ float red[256];
    int b = blockIdx.x;
    int t = threadIdx.x;
    float s = 0.0f;
    for (int d = t; d < DD; d += 256) s += h[(size_t)b * LL * DD + d] * Wc[d * NC];
    red[t] = s; __syncthreads();
    for (int o = 128; o > 0; o >>= 1) { if (t < o) red[t] += red[t + o]; __syncthreads(); }
    if (t == 0) out[b * NC] = red[0] + bc[0];
}

// ---------------- launcher ----------------
extern "C" void kernel_launch(void* const* d_in, const int* in_sizes, int n_in,
                              void* d_out, int out_size) {
    const int*   x    = (const int*)  d_in[0];
    const int*   mask = (const int*)  d_in[1];
    const float* emb  = (const float*)d_in[2];
    const float* Wq   = (const float*)d_in[3];
    const float* bq   = (const float*)d_in[4];
    const float* Wk   = (const float*)d_in[5];
    const float* bk   = (const float*)d_in[6];
    const float* Wv   = (const float*)d_in[7];
    const float* bv   = (const float*)d_in[8];
    const float* Wo   = (const float*)d_in[9];
    const float* bo   = (const float*)d_in[10];
    const float* W1   = (const float*)d_in[11];
    const float* b1   = (const float*)d_in[12];
    const float* W2   = (const float*)d_in[13];
    const float* b2   = (const float*)d_in[14];
    const float* g1   = (const float*)d_in[15];
    const float* be1  = (const float*)d_in[16];
    const float* g2   = (const float*)d_in[17];
    const float* be2  = (const float*)d_in[18];
    const float* Wc   = (const float*)d_in[19];
    const float* bc   = (const float*)d_in[20];

    float* out = (float*)d_out;
    float* logits = out;
    float* attn_base = out + (size_t)BB * NC;

    static bool attr_set = false;
    if (!attr_set) {
        cudaFuncSetAttribute(gemm_mma, cudaFuncAttributeMaxDynamicSharedMemorySize, GEMM_SMEM);
        cudaFuncSetAttribute(attn_tc, cudaFuncAttributeMaxDynamicSharedMemorySize, ATTN_SMEM);
        attr_set = true;
    }

    float *p_h, *p_bqkv;
    bf16 *p_xnh, *p_xnl, *p_qkvh, *p_qkvl, *p_aoh, *p_aol, *p_ffh, *p_ffl;
    bf16 *p_wqkvh, *p_wqkvl, *p_woh, *p_wol, *p_w1h, *p_w1l, *p_w2h, *p_w2l;
    cudaGetSymbolAddress((void**)&p_h, g_h);
    cudaGetSymbolAddress((void**)&p_bqkv, g_bqkv);
    cudaGetSymbolAddress((void**)&p_xnh, g_xnh); cudaGetSymbolAddress((void**)&p_xnl, g_xnl);
    cudaGetSymbolAddress((void**)&p_qkvh, g_qkvh); cudaGetSymbolAddress((void**)&p_qkvl, g_qkvl);
    cudaGetSymbolAddress((void**)&p_aoh, g_aoh); cudaGetSymbolAddress((void**)&p_aol, g_aol);
    cudaGetSymbolAddress((void**)&p_ffh, g_ffh); cudaGetSymbolAddress((void**)&p_ffl, g_ffl);
    cudaGetSymbolAddress((void**)&p_wqkvh, g_wqkvh); cudaGetSymbolAddress((void**)&p_wqkvl, g_wqkvl);
    cudaGetSymbolAddress((void**)&p_woh, g_woh); cudaGetSymbolAddress((void**)&p_wol, g_wol);
    cudaGetSymbolAddress((void**)&p_w1h, g_w1h); cudaGetSymbolAddress((void**)&p_w1l, g_w1l);
    cudaGetSymbolAddress((void**)&p_w2h, g_w2h); cudaGetSymbolAddress((void**)&p_w2l, g_w2l);

    dim3 tb(32, 8);
    size_t olsQKV = (size_t)NQKV * DD;
    tsplit_kernel<<<dim3(DD/32, DD/32, NL), tb>>>(Wq, p_wqkvh, p_wqkvl, DD, DD, 0,    olsQKV);
    tsplit_kernel<<<dim3(DD/32, DD/32, NL), tb>>>(Wk, p_wqkvh, p_wqkvl, DD, DD, 768,  olsQKV);
    tsplit_kernel<<<dim3(DD/32, DD/32, NL), tb>>>(Wv, p_wqkvh, p_wqkvl, DD, DD, 1536, olsQKV);
    tsplit_kernel<<<dim3(DD/32, DD/32, NL), tb>>>(Wo, p_woh, p_wol, DD, DD, 0, (size_t)DD*DD);
    tsplit_kernel<<<dim3(FF/32, DD/32, NL), tb>>>(W1, p_w1h, p_w1l, DD, FF, 0, (size_t)DD*FF);
    tsplit_kernel<<<dim3(DD/32, FF/32, NL), tb>>>(W2, p_w2h, p_w2l, FF, DD, 0, (size_t)FF*DD);
    bias_concat<<<dim3(NQKV/256, NL), 256>>>(bq, bk, bv, p_bqkv);

    embed_kernel<<<MM, 256>>>(x, emb, p_h);

    dim3 gD(DD/64, MM/128);
    dim3 gQKV(NQKV/64, MM/128);
    dim3 gF(FF/64, MM/128);
    dim3 gAttn(LL/64, HH, BB);

    for (int l = 0; l < NL; l++) {
        size_t wD = (size_t)l * DD * DD;
        size_t wF = (size_t)l * DD * FF;
        size_t wQ = (size_t)l * olsQKV;
        ln_kernel<<<MM, 256>>>(p_h, g1 + l*DD, be1 + l*DD, p_xnh, p_xnl);
        gemm_mma<<<gQKV, 256, GEMM_SMEM>>>(p_xnh, p_xnl, p_wqkvh + wQ, p_wqkvl + wQ,
                                           p_bqkv + l*NQKV, nullptr, p_qkvh, p_qkvl, NQKV, DD, 3);
        attn_tc<<<gAttn, 256, ATTN_SMEM>>>(p_qkvh, p_qkvl, mask,
                                           attn_base + (size_t)l * BB * HH * LL * LL, p_aoh, p_aol);
        gemm_mma<<<gD, 256, GEMM_SMEM>>>(p_aoh, p_aol, p_woh + wD, p_wol + wD, bo + l*DD,
                                         p_h, nullptr, nullptr, DD, DD, 2);
        ln_kernel<<<MM, 256>>>(p_h, g2 + l*DD, be2 + l*DD, p_xnh, p_xnl);
        gemm_mma<<<gF, 256, GEMM_SMEM>>>(p_xnh, p_xnl, p_w1h + wF, p_w1l + wF, b1 + l*FF,
                                         nullptr, p_ffh, p_ffl, FF, DD, 1);
        gemm_mma<<<gD, 256, GEMM_SMEM>>>(p_ffh, p_ffl, p_w2h + wF, p_w2l + wF, b2 + l*DD,
                                         p_h, nullptr, nullptr, DD, FF, 2);
    }

    logits_kernel<<<BB, 256>>>(p_h, Wc, bc, logits);
}